// round 14
// baseline (speedup 1.0000x reference)
#include <cuda_runtime.h>
#include <cuda_fp16.h>
#include <cstdint>

// Problem dims
#define Bq 16
#define Tq 512
#define Eq 256
#define Aq 8

// Scratch (allocation-free rules: __device__ globals)
__device__ float  g_gram[Bq * Tq * Tq];             // masked gram fp32
__device__ __half g_xh [Bq * Tq * Eq];              // X hi (B,T,E)
__device__ __half g_xl [Bq * Tq * Eq];              // X lo (gram 3-pass only)
__device__ __half g_xth[Bq * Eq * Tq];              // X^T hi (B,E,T)
__device__ __half g_attn_h[Bq * Aq * Tq * Tq];      // attn hi fp16 (av A operand)
__device__ __half g_aoh[Bq * Aq * Tq * Eq];         // attn_out hi (B,A,T,E)
__device__ __half g_wh [Eq * Aq * Eq];              // W hi
__device__ float  g_attn_fb[Bq * Aq * Tq * Tq];     // fallback fp32 attn buffer

// Base GEMM tiling: 128x128 CTA tile, k32 stages, 256 threads, 8 warps (4x2)
// smem matrix: rows x 80B (4 x 16B chunks + 16B pad -> ldmatrix conflict-free)
#define MATB 10240          // 128 rows x 80B
#define MATB256 20480       // 256 rows x 80B
#define NSTAGE 3
// av (128x256 tile): stage = A(128x80) + B(256x80) = 30720; 4 stages
#define AV_STAGE 30720
#define AV_NSTAGE 4

// ---------------------------------------------------------------------------
__device__ __forceinline__ uint32_t smem_u32(const void* p) {
    uint32_t a;
    asm("{ .reg .u64 t; cvta.to.shared.u64 t, %1; cvt.u32.u64 %0, t; }" : "=r"(a) : "l"(p));
    return a;
}
__device__ __forceinline__ void cp16(uint32_t dst, const void* src) {
    asm volatile("cp.async.cg.shared.global [%0], [%1], 16;"
                 :: "r"(dst), "l"(__cvta_generic_to_global(src)));
}
__device__ __forceinline__ void cp_commit() {
    asm volatile("cp.async.commit_group;");
}
template <int N>
__device__ __forceinline__ void cp_wait() {
    asm volatile("cp.async.wait_group %0;" :: "n"(N));
}
__device__ __forceinline__ void ldsm_x4(unsigned& r0, unsigned& r1, unsigned& r2,
                                        unsigned& r3, uint32_t addr) {
    asm volatile("ldmatrix.sync.aligned.m8n8.x4.shared.b16 {%0,%1,%2,%3}, [%4];"
                 : "=r"(r0), "=r"(r1), "=r"(r2), "=r"(r3) : "r"(addr));
}
__device__ __forceinline__ void mma16816(float* c, const unsigned* a, const unsigned* b) {
    asm volatile(
        "mma.sync.aligned.m16n8k16.row.col.f32.f16.f16.f32 "
        "{%0,%1,%2,%3}, {%4,%5,%6,%7}, {%8,%9}, {%0,%1,%2,%3};"
        : "+f"(c[0]), "+f"(c[1]), "+f"(c[2]), "+f"(c[3])
        : "r"(a[0]), "r"(a[1]), "r"(a[2]), "r"(a[3]), "r"(b[0]), "r"(b[1]));
}

// ---------------------------------------------------------------------------
// 128x128 MMA compute over one k32 stage (warp tile 32x64, 4x2 warp grid).
// NPASS==1: ah*bh only.        A at abase,       B at bbase.
// NPASS==3: + al*bh + ah*bl.   Al at abase+MATB, Bl at bbase+MATB.
// ---------------------------------------------------------------------------
template <int NPASS>
__device__ __forceinline__ void mma_stage(uint32_t abase, uint32_t bbase,
                                          float acc[2][8][4]) {
    const int lane = threadIdx.x & 31, wid = threadIdx.x >> 5;
    const int mw = (wid >> 1) * 32, nw = (wid & 1) * 64;
    const int lr = lane & 7, q = lane >> 3;
    const int a_ro = (q & 1) * 8 + lr, a_co = (q >> 1);
    const int b_ro = (q >> 1) * 8 + lr, b_co = (q & 1);
    #pragma unroll
    for (int ks = 0; ks < 2; ++ks) {
        unsigned ah[2][4], al[2][4];
        #pragma unroll
        for (int mt = 0; mt < 2; ++mt) {
            uint32_t ad = abase + (uint32_t)((mw + mt * 16 + a_ro) * 80 + (2 * ks + a_co) * 16);
            ldsm_x4(ah[mt][0], ah[mt][1], ah[mt][2], ah[mt][3], ad);
            if (NPASS == 3)
                ldsm_x4(al[mt][0], al[mt][1], al[mt][2], al[mt][3], ad + MATB);
        }
        unsigned bh[8][2], bl[8][2];
        #pragma unroll
        for (int np = 0; np < 4; ++np) {
            uint32_t bd = bbase + (uint32_t)((nw + np * 16 + b_ro) * 80 + (2 * ks + b_co) * 16);
            ldsm_x4(bh[2*np][0], bh[2*np][1], bh[2*np+1][0], bh[2*np+1][1], bd);
            if (NPASS == 3)
                ldsm_x4(bl[2*np][0], bl[2*np][1], bl[2*np+1][0], bl[2*np+1][1], bd + MATB);
        }
        #pragma unroll
        for (int nt = 0; nt < 8; ++nt)
            #pragma unroll
            for (int mt = 0; mt < 2; ++mt) {
                mma16816(acc[mt][nt], ah[mt], bh[nt]);
                if (NPASS == 3) {
                    mma16816(acc[mt][nt], al[mt], bh[nt]);
                    mma16816(acc[mt][nt], ah[mt], bl[nt]);
                }
            }
    }
}

// ---------------------------------------------------------------------------
// 128x128 mainloop: pre-split fp16 planes in gmem, all via cp.async.
// NPASS==1: stage = {Ah, Bh};  NPASS==3: stage = {Ah, Al, Bh, Bl}.
// ---------------------------------------------------------------------------
template <int NPASS>
__device__ __forceinline__ void mma_loop(
    const __half* __restrict__ Agh, const __half* __restrict__ Agl, int lda, int m0,
    const __half* __restrict__ Bgh, const __half* __restrict__ Bgl, int ldb, int n0,
    int kIters, char* smb, float acc[2][8][4])
{
    const int BOFF = (NPASS == 3 ? 2 : 1) * MATB;
    const int STAGE = (NPASS == 3 ? 4 : 2) * MATB;
    const int t = threadIdx.x;
    const int r = t >> 1, cb = (t & 1) * 2;
    const __half* pa_h = Agh + (size_t)(m0 + r) * lda + cb * 8;
    const __half* pa_l = (NPASS == 3) ? Agl + (size_t)(m0 + r) * lda + cb * 8 : pa_h;
    const __half* pb_h = Bgh + (size_t)(n0 + r) * ldb + cb * 8;
    const __half* pb_l = (NPASS == 3) ? Bgl + (size_t)(n0 + r) * ldb + cb * 8 : pb_h;
    const uint32_t sbase = smem_u32(smb);
    const uint32_t rowoff = (uint32_t)r * 80u + (uint32_t)cb * 16u;

    auto issue = [&](int it) {
        uint32_t sb = sbase + (uint32_t)((it % NSTAGE) * STAGE) + rowoff;
        int k0 = it * 32;
        #pragma unroll
        for (int j = 0; j < 2; ++j) {
            cp16(sb + j * 16,        pa_h + k0 + j * 8);
            cp16(sb + BOFF + j * 16, pb_h + k0 + j * 8);
            if (NPASS == 3) {
                cp16(sb + MATB + j * 16,     pa_l + k0 + j * 8);
                cp16(sb + 3 * MATB + j * 16, pb_l + k0 + j * 8);
            }
        }
    };
    issue(0); cp_commit();
    issue(1); cp_commit();

    for (int it = 0; it < kIters; ++it) {
        cp_wait<1>();
        __syncthreads();
        if (it + 2 < kIters) issue(it + 2);
        cp_commit();
        uint32_t sb = sbase + (uint32_t)((it % NSTAGE) * STAGE);
        mma_stage<NPASS>(sb, sb + BOFF, acc);
    }
}

// ---------------------------------------------------------------------------
// av mainloop: CTA 128(m) x 256(n), warp tile 64x64 (2x4 warp grid), 1-pass.
// Stage = A(128x32) + B(256x32) fp16; 4-stage cp.async pipeline.
// LDSM/MMA = 8/32 per warp-k16 (vs 12/32 for the 128x128 tile).
// ---------------------------------------------------------------------------
__device__ __forceinline__ void mma_loop_av(
    const __half* __restrict__ Agh, int lda, int m0,
    const __half* __restrict__ Bgh, int ldb,
    int kIters, char* smb, float acc[4][8][4])
{
    const int t = threadIdx.x;
    const int r = t >> 1, cb = (t & 1) * 2;
    const __half* pa = Agh + (size_t)(m0 + r) * lda + cb * 8;
    const __half* pb = Bgh + (size_t)t * ldb;      // B row = thread id (0..255)
    const uint32_t sbase = smem_u32(smb);
    const uint32_t a_off = (uint32_t)r * 80u + (uint32_t)cb * 16u;
    const uint32_t b_off = 10240u + (uint32_t)t * 80u;

    auto issue = [&](int it) {
        uint32_t sb = sbase + (uint32_t)((it & 3) * AV_STAGE);
        int k0 = it * 32;
        cp16(sb + a_off,      pa + k0);
        cp16(sb + a_off + 16, pa + k0 + 8);
        #pragma unroll
        for (int j = 0; j < 4; ++j)
            cp16(sb + b_off + j * 16, pb + k0 + j * 8);
    };
    issue(0); cp_commit();
    issue(1); cp_commit();
    issue(2); cp_commit();

    const int lane = t & 31, wid = t >> 5;
    const int mw = (wid >> 2) * 64, nw = (wid & 3) * 64;
    const int lr = lane & 7, q = lane >> 3;
    const int a_ro = (q & 1) * 8 + lr, a_co = (q >> 1);
    const int b_ro = (q >> 1) * 8 + lr, b_co = (q & 1);

    for (int it = 0; it < kIters; ++it) {
        cp_wait<2>();
        __syncthreads();
        if (it + 3 < kIters) issue(it + 3);
        cp_commit();
        uint32_t abase = sbase + (uint32_t)((it & 3) * AV_STAGE);
        uint32_t bbase = abase + 10240u;
        #pragma unroll
        for (int ks = 0; ks < 2; ++ks) {
            unsigned a[4][4];
            #pragma unroll
            for (int mt = 0; mt < 4; ++mt) {
                uint32_t ad = abase +
                    (uint32_t)((mw + mt * 16 + a_ro) * 80 + (2 * ks + a_co) * 16);
                ldsm_x4(a[mt][0], a[mt][1], a[mt][2], a[mt][3], ad);
            }
            #pragma unroll
            for (int np = 0; np < 4; ++np) {
                unsigned b0[2], b1[2];
                uint32_t bd = bbase +
                    (uint32_t)((nw + np * 16 + b_ro) * 80 + (2 * ks + b_co) * 16);
                ldsm_x4(b0[0], b0[1], b1[0], b1[1], bd);
                #pragma unroll
                for (int mt = 0; mt < 4; ++mt) {
                    mma16816(acc[mt][2 * np],     a[mt], b0);
                    mma16816(acc[mt][2 * np + 1], a[mt], b1);
                }
            }
        }
    }
}

// ---------------------------------------------------------------------------
// Kernel 0a: X -> Xh, Xl (B,T,E) and Xth (B,E,T)
// ---------------------------------------------------------------------------
__global__ void prep_x_kernel(const float* __restrict__ X) {
    __shared__ float tile[32][33];
    int b = blockIdx.z;
    int e0 = blockIdx.x * 32, t0 = blockIdx.y * 32;
    const float* Xb = X + (size_t)b * Tq * Eq;
    int tx = threadIdx.x, ty = threadIdx.y;  // 32x8
    #pragma unroll
    for (int i = 0; i < 32; i += 8) {
        float v = Xb[(size_t)(t0 + ty + i) * Eq + e0 + tx];
        tile[ty + i][tx] = v;
        __half h = __float2half_rn(v);
        __half l = __float2half_rn(v - __half2float(h));
        size_t idx = ((size_t)b * Tq + t0 + ty + i) * Eq + e0 + tx;
        g_xh[idx] = h;
        g_xl[idx] = l;
    }
    __syncthreads();
    #pragma unroll
    for (int i = 0; i < 32; i += 8) {
        float v = tile[tx][ty + i];
        g_xth[((size_t)b * Eq + e0 + ty + i) * Tq + t0 + tx] = __float2half_rn(v);
    }
}

// Kernel 0b: W -> Wh
__global__ void prep_w_kernel(const float* __restrict__ W) {
    int idx = blockIdx.x * 256 + threadIdx.x;
    g_wh[idx] = __float2half_rn(W[idx]);
}

// ---------------------------------------------------------------------------
// Kernel 1: G_b = mask-outer ? (X_b X_b^T)/sqrt(E) : 0   (3-pass fp16, K=256)
// ---------------------------------------------------------------------------
__global__ __launch_bounds__(256, 1)
void gram_kernel(const int* __restrict__ mask) {
    extern __shared__ char smb[];
    int b = blockIdx.z;
    int m0 = blockIdx.y * 128, n0 = blockIdx.x * 128;
    const __half* Xh = g_xh + (size_t)b * Tq * Eq;
    const __half* Xl = g_xl + (size_t)b * Tq * Eq;
    float acc[2][8][4] = {};
    mma_loop<3>(Xh, Xl, Eq, m0, Xh, Xl, Eq, n0, Eq / 32, smb, acc);

    const int lane = threadIdx.x & 31, wid = threadIdx.x >> 5;
    const int gid = lane >> 2, tig = lane & 3;
    const int mw = (wid >> 1) * 32, nw = (wid & 1) * 64;
    const int* mb = mask + b * Tq;
    float* G = g_gram + (size_t)b * Tq * Tq;
    #pragma unroll
    for (int mt = 0; mt < 2; ++mt) {
        int mr0 = m0 + mw + mt * 16 + gid;
        int mr1 = mr0 + 8;
        float s0 = (mb[mr0] != 0) ? 0.0625f : 0.0f;   // 1/sqrt(256), fold row mask
        float s1 = (mb[mr1] != 0) ? 0.0625f : 0.0f;
        #pragma unroll
        for (int nt = 0; nt < 8; ++nt) {
            int col = n0 + nw + nt * 8 + 2 * tig;
            float c0 = (mb[col] != 0) ? 1.0f : 0.0f;
            float c1 = (mb[col + 1] != 0) ? 1.0f : 0.0f;
            *(float2*)&G[(size_t)mr0 * Tq + col] =
                make_float2(acc[mt][nt][0] * s0 * c0, acc[mt][nt][1] * s0 * c1);
            *(float2*)&G[(size_t)mr1 * Tq + col] =
                make_float2(acc[mt][nt][2] * s1 * c0, acc[mt][nt][3] * s1 * c1);
        }
    }
}

// ---------------------------------------------------------------------------
// Kernel 2: softmax, warp-per-attribute; zero barriers; writes fp32 + fp16 hi
// ---------------------------------------------------------------------------
__global__ __launch_bounds__(256, 8)
void softmax_kernel(const float* __restrict__ atr, float* __restrict__ attn) {
    int t = blockIdx.x, b = blockIdx.y;
    int wid = threadIdx.x >> 5, lane = threadIdx.x & 31;
    const float4* g4 = (const float4*)(g_gram + ((size_t)b * Tq + t) * Tq);
    float4 v[4];
    #pragma unroll
    for (int j = 0; j < 4; ++j) v[j] = g4[lane + 32 * j];

    float m = v[0].x;
    #pragma unroll
    for (int j = 0; j < 4; ++j) {
        m = fmaxf(m, fmaxf(fmaxf(v[j].x, v[j].y), fmaxf(v[j].z, v[j].w)));
    }
    #pragma unroll
    for (int off = 16; off; off >>= 1) m = fmaxf(m, __shfl_xor_sync(0xffffffffu, m, off));

    float s = atr[b * Aq + wid];
    float s2 = s * s;
    float4 e[4];
    float sum = 0.0f;
    #pragma unroll
    for (int j = 0; j < 4; ++j) {
        e[j].x = __expf(s2 * (v[j].x - m));
        e[j].y = __expf(s2 * (v[j].y - m));
        e[j].z = __expf(s2 * (v[j].z - m));
        e[j].w = __expf(s2 * (v[j].w - m));
        sum += e[j].x + e[j].y + e[j].z + e[j].w;
    }
    #pragma unroll
    for (int off = 16; off; off >>= 1) sum += __shfl_xor_sync(0xffffffffu, sum, off);
    float inv = 1.0f / sum;

    size_t rowbase = (((size_t)(b * Aq + wid) * Tq) + t) * Tq;
    float4* o4 = (float4*)(attn + rowbase);
    uint2*  h2 = (uint2*)(g_attn_h + rowbase);
    #pragma unroll
    for (int j = 0; j < 4; ++j) {
        float4 o = make_float4(e[j].x * inv, e[j].y * inv, e[j].z * inv, e[j].w * inv);
        o4[lane + 32 * j] = o;
        __half2 ha = __float22half2_rn(make_float2(o.x, o.y));
        __half2 hb = __float22half2_rn(make_float2(o.z, o.w));
        h2[lane + 32 * j] = make_uint2(*(unsigned*)&ha, *(unsigned*)&hb);
    }
}

// ---------------------------------------------------------------------------
// Kernel 3: attn_out[ba] = s_ba * (attn_ba @ X_b); CTA 128x256, warp 64x64
// ---------------------------------------------------------------------------
__global__ __launch_bounds__(256, 1)
void av_kernel(const float* __restrict__ atr) {
    extern __shared__ char smb[];
    int ba = blockIdx.z, b = ba >> 3;
    int m0 = blockIdx.y * 128;
    const __half* Ah = g_attn_h + (size_t)ba * Tq * Tq;
    const __half* Bh = g_xth + (size_t)b * Eq * Tq;
    float acc[4][8][4] = {};
    mma_loop_av(Ah, Tq, m0, Bh, Tq, Tq / 32, smb, acc);

    const int lane = threadIdx.x & 31, wid = threadIdx.x >> 5;
    const int gid = lane >> 2, tig = lane & 3;
    const int mw = (wid >> 2) * 64, nw = (wid & 3) * 64;
    float sc = atr[ba];
    #pragma unroll
    for (int mt = 0; mt < 4; ++mt) {
        int mr0 = m0 + mw + mt * 16 + gid;
        int mr1 = mr0 + 8;
        #pragma unroll
        for (int nt = 0; nt < 8; ++nt) {
            int col = nw + nt * 8 + 2 * tig;
            size_t i0 = ((size_t)ba * Tq + mr0) * Eq + col;
            size_t i1 = ((size_t)ba * Tq + mr1) * Eq + col;
            *(__half2*)&g_aoh[i0] = __float22half2_rn(
                make_float2(sc * acc[mt][nt][0], sc * acc[mt][nt][1]));
            *(__half2*)&g_aoh[i1] = __float22half2_rn(
                make_float2(sc * acc[mt][nt][2], sc * acc[mt][nt][3]));
        }
    }
}

// ---------------------------------------------------------------------------
// Kernel 4: out = aoh(8192x2048) @ Wh^T(2048x256) + bias (full K, 1-pass)
// ---------------------------------------------------------------------------
__global__ __launch_bounds__(256, 2)
void proj_kernel(const float* __restrict__ bias, float* __restrict__ out) {
    extern __shared__ char smb[];
    const int Kd = Aq * Eq;  // 2048
    int m0 = blockIdx.y * 128, n0 = blockIdx.x * 128;
    float acc[2][8][4] = {};
    mma_loop<1>(g_aoh, nullptr, Kd, m0, g_wh, nullptr, Kd, n0, Kd / 32, smb, acc);

    const int lane = threadIdx.x & 31, wid = threadIdx.x >> 5;
    const int gid = lane >> 2, tig = lane & 3;
    const int mw = (wid >> 1) * 32, nw = (wid & 1) * 64;
    #pragma unroll
    for (int mt = 0; mt < 2; ++mt) {
        int mr0 = m0 + mw + mt * 16 + gid;
        int mr1 = mr0 + 8;
        #pragma unroll
        for (int nt = 0; nt < 8; ++nt) {
            int col = n0 + nw + nt * 8 + 2 * tig;
            float b0 = bias[col], b1 = bias[col + 1];
            *(float2*)&out[(size_t)mr0 * Eq + col] =
                make_float2(acc[mt][nt][0] + b0, acc[mt][nt][1] + b1);
            *(float2*)&out[(size_t)mr1 * Eq + col] =
                make_float2(acc[mt][nt][2] + b0, acc[mt][nt][3] + b1);
        }
    }
}

// ---------------------------------------------------------------------------
extern "C" void kernel_launch(void* const* d_in, const int* in_sizes, int n_in,
                              void* d_out, int out_size) {
    const float* sent = (const float*)d_in[0];
    const int*   mask = (const int*)d_in[1];
    const float* atr  = (const float*)d_in[2];
    const float* W    = (const float*)d_in[3];
    const float* bias = (const float*)d_in[4];
    float* out = (float*)d_out;

    const long long OUT_E  = (long long)Bq * Tq * Eq;        // 2,097,152
    const long long ATTN_E = (long long)Bq * Aq * Tq * Tq;   // 33,554,432

    float* attn_ptr;
    if ((long long)out_size >= OUT_E + ATTN_E) {
        attn_ptr = out + OUT_E;                  // tuple (output, attn) flattened
    } else {
        void* p = nullptr;
        cudaGetSymbolAddress(&p, g_attn_fb);     // query only, capture-safe
        attn_ptr = (float*)p;
    }

    const int SM3  = 3 * 4 * MATB;          // 122880 (gram 3-pass)
    const int SM1  = 3 * 2 * MATB;          // 61440  (proj 1-pass)
    const int SMAV = AV_NSTAGE * AV_STAGE;  // 122880 (av 128x256, 4 stages)
    cudaFuncSetAttribute(gram_kernel, cudaFuncAttributeMaxDynamicSharedMemorySize, SM3);
    cudaFuncSetAttribute(av_kernel,   cudaFuncAttributeMaxDynamicSharedMemorySize, SMAV);
    cudaFuncSetAttribute(proj_kernel, cudaFuncAttributeMaxDynamicSharedMemorySize, SM1);

    prep_x_kernel<<<dim3(Eq / 32, Tq / 32, Bq), dim3(32, 8)>>>(sent);
    prep_w_kernel<<<(Eq * Aq * Eq) / 256, 256>>>(W);
    gram_kernel<<<dim3(Tq / 128, Tq / 128, Bq), 256, SM3>>>(mask);
    softmax_kernel<<<dim3(Tq, Bq), 256>>>(atr, attn_ptr);
    av_kernel<<<dim3(1, Tq / 128, Bq * Aq), 256, SMAV>>>(atr);
    proj_kernel<<<dim3(Eq / 128, (Bq * Tq) / 128, 1), 256, SM1>>>(bias, out);
}

// round 15
// speedup vs baseline: 1.1351x; 1.1351x over previous
#include <cuda_runtime.h>
#include <cuda_fp16.h>
#include <cstdint>

// Problem dims
#define Bq 16
#define Tq 512
#define Eq 256
#define Aq 8

// Scratch (allocation-free rules: __device__ globals)
__device__ float  g_gram[Bq * Tq * Tq];             // masked gram fp32
__device__ __half g_xh [Bq * Tq * Eq];              // X hi (B,T,E)
__device__ __half g_xl [Bq * Tq * Eq];              // X lo (gram 3-pass only)
__device__ __half g_xth[Bq * Eq * Tq];              // X^T hi (B,E,T)
__device__ __half g_attn_h[Bq * Aq * Tq * Tq];      // attn hi fp16 (av A operand)
__device__ __half g_aoh[Bq * Aq * Tq * Eq];         // attn_out hi (B,A,T,E)
__device__ __half g_wh [Eq * Aq * Eq];              // W hi
__device__ float  g_attn_fb[Bq * Aq * Tq * Tq];     // fallback fp32 attn buffer

// GEMM tiling: 128x128 CTA tile, k32 fp-elem stages, 256 threads, 8 warps (4x2)
// smem matrix: 128 rows x 80B (4 x 16B chunks + 16B pad -> ldmatrix conflict-free)
// 1-pass kernels (av/proj): 4-stage cp.async pipeline, 81920 B -> 2 CTAs/SM.
// 3-pass kernel (gram): 3-stage, 122880 B -> 1 CTA/SM.
#define MATB 10240

// ---------------------------------------------------------------------------
__device__ __forceinline__ uint32_t smem_u32(const void* p) {
    uint32_t a;
    asm("{ .reg .u64 t; cvta.to.shared.u64 t, %1; cvt.u32.u64 %0, t; }" : "=r"(a) : "l"(p));
    return a;
}
__device__ __forceinline__ void cp16(uint32_t dst, const void* src) {
    asm volatile("cp.async.cg.shared.global [%0], [%1], 16;"
                 :: "r"(dst), "l"(__cvta_generic_to_global(src)));
}
__device__ __forceinline__ void cp_commit() {
    asm volatile("cp.async.commit_group;");
}
template <int N>
__device__ __forceinline__ void cp_wait() {
    asm volatile("cp.async.wait_group %0;" :: "n"(N));
}
__device__ __forceinline__ void ldsm_x4(unsigned& r0, unsigned& r1, unsigned& r2,
                                        unsigned& r3, uint32_t addr) {
    asm volatile("ldmatrix.sync.aligned.m8n8.x4.shared.b16 {%0,%1,%2,%3}, [%4];"
                 : "=r"(r0), "=r"(r1), "=r"(r2), "=r"(r3) : "r"(addr));
}
__device__ __forceinline__ void mma16816(float* c, const unsigned* a, const unsigned* b) {
    asm volatile(
        "mma.sync.aligned.m16n8k16.row.col.f32.f16.f16.f32 "
        "{%0,%1,%2,%3}, {%4,%5,%6,%7}, {%8,%9}, {%0,%1,%2,%3};"
        : "+f"(c[0]), "+f"(c[1]), "+f"(c[2]), "+f"(c[3])
        : "r"(a[0]), "r"(a[1]), "r"(a[2]), "r"(a[3]), "r"(b[0]), "r"(b[1]));
}

// ---------------------------------------------------------------------------
// MMA compute over one k32 stage (warp tile 32x64, 4x2 warp grid).
// NPASS==1: ah*bh only.        A at abase,       B at bbase.
// NPASS==3: + al*bh + ah*bl.   Al at abase+MATB, Bl at bbase+MATB.
// ---------------------------------------------------------------------------
template <int NPASS>
__device__ __forceinline__ void mma_stage(uint32_t abase, uint32_t bbase,
                                          float acc[2][8][4]) {
    const int lane = threadIdx.x & 31, wid = threadIdx.x >> 5;
    const int mw = (wid >> 1) * 32, nw = (wid & 1) * 64;
    const int lr = lane & 7, q = lane >> 3;
    const int a_ro = (q & 1) * 8 + lr, a_co = (q >> 1);
    const int b_ro = (q >> 1) * 8 + lr, b_co = (q & 1);
    #pragma unroll
    for (int ks = 0; ks < 2; ++ks) {
        unsigned ah[2][4], al[2][4];
        #pragma unroll
        for (int mt = 0; mt < 2; ++mt) {
            uint32_t ad = abase + (uint32_t)((mw + mt * 16 + a_ro) * 80 + (2 * ks + a_co) * 16);
            ldsm_x4(ah[mt][0], ah[mt][1], ah[mt][2], ah[mt][3], ad);
            if (NPASS == 3)
                ldsm_x4(al[mt][0], al[mt][1], al[mt][2], al[mt][3], ad + MATB);
        }
        unsigned bh[8][2], bl[8][2];
        #pragma unroll
        for (int np = 0; np < 4; ++np) {
            uint32_t bd = bbase + (uint32_t)((nw + np * 16 + b_ro) * 80 + (2 * ks + b_co) * 16);
            ldsm_x4(bh[2*np][0], bh[2*np][1], bh[2*np+1][0], bh[2*np+1][1], bd);
            if (NPASS == 3)
                ldsm_x4(bl[2*np][0], bl[2*np][1], bl[2*np+1][0], bl[2*np+1][1], bd + MATB);
        }
        #pragma unroll
        for (int nt = 0; nt < 8; ++nt)
            #pragma unroll
            for (int mt = 0; mt < 2; ++mt) {
                mma16816(acc[mt][nt], ah[mt], bh[nt]);
                if (NPASS == 3) {
                    mma16816(acc[mt][nt], al[mt], bh[nt]);
                    mma16816(acc[mt][nt], ah[mt], bl[nt]);
                }
            }
    }
}

// ---------------------------------------------------------------------------
// Mainloop: pre-split fp16 planes in gmem, all via cp.async.
// NPASS==1: stage = {Ah, Bh}, 4-stage pipeline (2 CTAs/SM).
// NPASS==3: stage = {Ah, Al, Bh, Bl}, 3-stage pipeline (1 CTA/SM).
// ---------------------------------------------------------------------------
template <int NPASS>
__device__ __forceinline__ void mma_loop(
    const __half* __restrict__ Agh, const __half* __restrict__ Agl, int lda, int m0,
    const __half* __restrict__ Bgh, const __half* __restrict__ Bgl, int ldb, int n0,
    int kIters, char* smb, float acc[2][8][4])
{
    const int BOFF  = (NPASS == 3 ? 2 : 1) * MATB;
    const int STAGE = (NPASS == 3 ? 4 : 2) * MATB;
    const int NSTG  = (NPASS == 3 ? 3 : 4);
    const int t = threadIdx.x;
    const int r = t >> 1, cb = (t & 1) * 2;
    const __half* pa_h = Agh + (size_t)(m0 + r) * lda + cb * 8;
    const __half* pa_l = (NPASS == 3) ? Agl + (size_t)(m0 + r) * lda + cb * 8 : pa_h;
    const __half* pb_h = Bgh + (size_t)(n0 + r) * ldb + cb * 8;
    const __half* pb_l = (NPASS == 3) ? Bgl + (size_t)(n0 + r) * ldb + cb * 8 : pb_h;
    const uint32_t sbase = smem_u32(smb);
    const uint32_t rowoff = (uint32_t)r * 80u + (uint32_t)cb * 16u;

    auto issue = [&](int it) {
        uint32_t sb = sbase + (uint32_t)((it % NSTG) * STAGE) + rowoff;
        int k0 = it * 32;
        #pragma unroll
        for (int j = 0; j < 2; ++j) {
            cp16(sb + j * 16,        pa_h + k0 + j * 8);
            cp16(sb + BOFF + j * 16, pb_h + k0 + j * 8);
            if (NPASS == 3) {
                cp16(sb + MATB + j * 16,     pa_l + k0 + j * 8);
                cp16(sb + 3 * MATB + j * 16, pb_l + k0 + j * 8);
            }
        }
    };
    #pragma unroll
    for (int p = 0; p < NSTG - 1; ++p) { issue(p); cp_commit(); }

    for (int it = 0; it < kIters; ++it) {
        cp_wait<NSTG - 2>();
        __syncthreads();
        if (it + NSTG - 1 < kIters) issue(it + NSTG - 1);
        cp_commit();
        uint32_t sb = sbase + (uint32_t)((it % NSTG) * STAGE);
        mma_stage<NPASS>(sb, sb + BOFF, acc);
    }
}

// ---------------------------------------------------------------------------
// Kernel 0a: X -> Xh, Xl (B,T,E) and Xth (B,E,T)
// ---------------------------------------------------------------------------
__global__ void prep_x_kernel(const float* __restrict__ X) {
    __shared__ float tile[32][33];
    int b = blockIdx.z;
    int e0 = blockIdx.x * 32, t0 = blockIdx.y * 32;
    const float* Xb = X + (size_t)b * Tq * Eq;
    int tx = threadIdx.x, ty = threadIdx.y;  // 32x8
    #pragma unroll
    for (int i = 0; i < 32; i += 8) {
        float v = Xb[(size_t)(t0 + ty + i) * Eq + e0 + tx];
        tile[ty + i][tx] = v;
        __half h = __float2half_rn(v);
        __half l = __float2half_rn(v - __half2float(h));
        size_t idx = ((size_t)b * Tq + t0 + ty + i) * Eq + e0 + tx;
        g_xh[idx] = h;
        g_xl[idx] = l;
    }
    __syncthreads();
    #pragma unroll
    for (int i = 0; i < 32; i += 8) {
        float v = tile[tx][ty + i];
        g_xth[((size_t)b * Eq + e0 + ty + i) * Tq + t0 + tx] = __float2half_rn(v);
    }
}

// Kernel 0b: W -> Wh
__global__ void prep_w_kernel(const float* __restrict__ W) {
    int idx = blockIdx.x * 256 + threadIdx.x;
    g_wh[idx] = __float2half_rn(W[idx]);
}

// ---------------------------------------------------------------------------
// Kernel 1: G_b = mask-outer ? (X_b X_b^T)/sqrt(E) : 0   (3-pass fp16, K=256)
// ---------------------------------------------------------------------------
__global__ __launch_bounds__(256, 1)
void gram_kernel(const int* __restrict__ mask) {
    extern __shared__ char smb[];
    int b = blockIdx.z;
    int m0 = blockIdx.y * 128, n0 = blockIdx.x * 128;
    const __half* Xh = g_xh + (size_t)b * Tq * Eq;
    const __half* Xl = g_xl + (size_t)b * Tq * Eq;
    float acc[2][8][4] = {};
    mma_loop<3>(Xh, Xl, Eq, m0, Xh, Xl, Eq, n0, Eq / 32, smb, acc);

    const int lane = threadIdx.x & 31, wid = threadIdx.x >> 5;
    const int gid = lane >> 2, tig = lane & 3;
    const int mw = (wid >> 1) * 32, nw = (wid & 1) * 64;
    const int* mb = mask + b * Tq;
    float* G = g_gram + (size_t)b * Tq * Tq;
    #pragma unroll
    for (int mt = 0; mt < 2; ++mt) {
        int mr0 = m0 + mw + mt * 16 + gid;
        int mr1 = mr0 + 8;
        float s0 = (mb[mr0] != 0) ? 0.0625f : 0.0f;   // 1/sqrt(256), fold row mask
        float s1 = (mb[mr1] != 0) ? 0.0625f : 0.0f;
        #pragma unroll
        for (int nt = 0; nt < 8; ++nt) {
            int col = n0 + nw + nt * 8 + 2 * tig;
            float c0 = (mb[col] != 0) ? 1.0f : 0.0f;
            float c1 = (mb[col + 1] != 0) ? 1.0f : 0.0f;
            *(float2*)&G[(size_t)mr0 * Tq + col] =
                make_float2(acc[mt][nt][0] * s0 * c0, acc[mt][nt][1] * s0 * c1);
            *(float2*)&G[(size_t)mr1 * Tq + col] =
                make_float2(acc[mt][nt][2] * s1 * c0, acc[mt][nt][3] * s1 * c1);
        }
    }
}

// ---------------------------------------------------------------------------
// Kernel 2: softmax, warp-per-attribute; zero barriers; writes fp32 + fp16 hi
// ---------------------------------------------------------------------------
__global__ __launch_bounds__(256, 8)
void softmax_kernel(const float* __restrict__ atr, float* __restrict__ attn) {
    int t = blockIdx.x, b = blockIdx.y;
    int wid = threadIdx.x >> 5, lane = threadIdx.x & 31;
    const float4* g4 = (const float4*)(g_gram + ((size_t)b * Tq + t) * Tq);
    float4 v[4];
    #pragma unroll
    for (int j = 0; j < 4; ++j) v[j] = g4[lane + 32 * j];

    float m = v[0].x;
    #pragma unroll
    for (int j = 0; j < 4; ++j) {
        m = fmaxf(m, fmaxf(fmaxf(v[j].x, v[j].y), fmaxf(v[j].z, v[j].w)));
    }
    #pragma unroll
    for (int off = 16; off; off >>= 1) m = fmaxf(m, __shfl_xor_sync(0xffffffffu, m, off));

    float s = atr[b * Aq + wid];
    float s2 = s * s;
    float4 e[4];
    float sum = 0.0f;
    #pragma unroll
    for (int j = 0; j < 4; ++j) {
        e[j].x = __expf(s2 * (v[j].x - m));
        e[j].y = __expf(s2 * (v[j].y - m));
        e[j].z = __expf(s2 * (v[j].z - m));
        e[j].w = __expf(s2 * (v[j].w - m));
        sum += e[j].x + e[j].y + e[j].z + e[j].w;
    }
    #pragma unroll
    for (int off = 16; off; off >>= 1) sum += __shfl_xor_sync(0xffffffffu, sum, off);
    float inv = 1.0f / sum;

    size_t rowbase = (((size_t)(b * Aq + wid) * Tq) + t) * Tq;
    float4* o4 = (float4*)(attn + rowbase);
    uint2*  h2 = (uint2*)(g_attn_h + rowbase);
    #pragma unroll
    for (int j = 0; j < 4; ++j) {
        float4 o = make_float4(e[j].x * inv, e[j].y * inv, e[j].z * inv, e[j].w * inv);
        o4[lane + 32 * j] = o;
        __half2 ha = __float22half2_rn(make_float2(o.x, o.y));
        __half2 hb = __float22half2_rn(make_float2(o.z, o.w));
        h2[lane + 32 * j] = make_uint2(*(unsigned*)&ha, *(unsigned*)&hb);
    }
}

// ---------------------------------------------------------------------------
// Kernel 3: attn_out[ba] = s_ba * (attn_ba @ X_b); 128x128, 1-pass, 4-stage
// ---------------------------------------------------------------------------
__global__ __launch_bounds__(256, 2)
void av_kernel(const float* __restrict__ atr) {
    extern __shared__ char smb[];
    int ba = blockIdx.z, b = ba >> 3;
    int m0 = blockIdx.y * 128, n0 = blockIdx.x * 128;
    const __half* Ah = g_attn_h + (size_t)ba * Tq * Tq;
    const __half* Bh = g_xth + (size_t)b * Eq * Tq;
    float acc[2][8][4] = {};
    mma_loop<1>(Ah, nullptr, Tq, m0, Bh, nullptr, Tq, n0, Tq / 32, smb, acc);

    const int lane = threadIdx.x & 31, wid = threadIdx.x >> 5;
    const int gid = lane >> 2, tig = lane & 3;
    const int mw = (wid >> 1) * 32, nw = (wid & 1) * 64;
    float sc = atr[ba];
    #pragma unroll
    for (int mt = 0; mt < 2; ++mt) {
        int mr0 = m0 + mw + mt * 16 + gid;
        int mr1 = mr0 + 8;
        #pragma unroll
        for (int nt = 0; nt < 8; ++nt) {
            int col = n0 + nw + nt * 8 + 2 * tig;
            size_t i0 = ((size_t)ba * Tq + mr0) * Eq + col;
            size_t i1 = ((size_t)ba * Tq + mr1) * Eq + col;
            *(__half2*)&g_aoh[i0] = __float22half2_rn(
                make_float2(sc * acc[mt][nt][0], sc * acc[mt][nt][1]));
            *(__half2*)&g_aoh[i1] = __float22half2_rn(
                make_float2(sc * acc[mt][nt][2], sc * acc[mt][nt][3]));
        }
    }
}

// ---------------------------------------------------------------------------
// Kernel 4: out = aoh(8192x2048) @ Wh^T(2048x256) + bias (full K, 1-pass, 4-stage)
// ---------------------------------------------------------------------------
__global__ __launch_bounds__(256, 2)
void proj_kernel(const float* __restrict__ bias, float* __restrict__ out) {
    extern __shared__ char smb[];
    const int Kd = Aq * Eq;  // 2048
    int m0 = blockIdx.y * 128, n0 = blockIdx.x * 128;
    float acc[2][8][4] = {};
    mma_loop<1>(g_aoh, nullptr, Kd, m0, g_wh, nullptr, Kd, n0, Kd / 32, smb, acc);

    const int lane = threadIdx.x & 31, wid = threadIdx.x >> 5;
    const int gid = lane >> 2, tig = lane & 3;
    const int mw = (wid >> 1) * 32, nw = (wid & 1) * 64;
    #pragma unroll
    for (int mt = 0; mt < 2; ++mt) {
        int mr0 = m0 + mw + mt * 16 + gid;
        int mr1 = mr0 + 8;
        #pragma unroll
        for (int nt = 0; nt < 8; ++nt) {
            int col = n0 + nw + nt * 8 + 2 * tig;
            float b0 = bias[col], b1 = bias[col + 1];
            *(float2*)&out[(size_t)mr0 * Eq + col] =
                make_float2(acc[mt][nt][0] + b0, acc[mt][nt][1] + b1);
            *(float2*)&out[(size_t)mr1 * Eq + col] =
                make_float2(acc[mt][nt][2] + b0, acc[mt][nt][3] + b1);
        }
    }
}

// ---------------------------------------------------------------------------
extern "C" void kernel_launch(void* const* d_in, const int* in_sizes, int n_in,
                              void* d_out, int out_size) {
    const float* sent = (const float*)d_in[0];
    const int*   mask = (const int*)d_in[1];
    const float* atr  = (const float*)d_in[2];
    const float* W    = (const float*)d_in[3];
    const float* bias = (const float*)d_in[4];
    float* out = (float*)d_out;

    const long long OUT_E  = (long long)Bq * Tq * Eq;        // 2,097,152
    const long long ATTN_E = (long long)Bq * Aq * Tq * Tq;   // 33,554,432

    float* attn_ptr;
    if ((long long)out_size >= OUT_E + ATTN_E) {
        attn_ptr = out + OUT_E;                  // tuple (output, attn) flattened
    } else {
        void* p = nullptr;
        cudaGetSymbolAddress(&p, g_attn_fb);     // query only, capture-safe
        attn_ptr = (float*)p;
    }

    const int SM3 = 3 * 4 * MATB;   // 122880 (gram 3-pass: 3 stages x 4 mats)
    const int SM1 = 4 * 2 * MATB;   // 81920  (1-pass: 4 stages x 2 mats, 2 CTAs/SM)
    cudaFuncSetAttribute(gram_kernel, cudaFuncAttributeMaxDynamicSharedMemorySize, SM3);
    cudaFuncSetAttribute(av_kernel,   cudaFuncAttributeMaxDynamicSharedMemorySize, SM1);
    cudaFuncSetAttribute(proj_kernel, cudaFuncAttributeMaxDynamicSharedMemorySize, SM1);

    prep_x_kernel<<<dim3(Eq / 32, Tq / 32, Bq), dim3(32, 8)>>>(sent);
    prep_w_kernel<<<(Eq * Aq * Eq) / 256, 256>>>(W);
    gram_kernel<<<dim3(Tq / 128, Tq / 128, Bq), 256, SM3>>>(mask);
    softmax_kernel<<<dim3(Tq, Bq), 256>>>(atr, attn_ptr);
    av_kernel<<<dim3(Eq / 128, Tq / 128, Bq * Aq), 256, SM1>>>(atr);
    proj_kernel<<<dim3(Eq / 128, (Bq * Tq) / 128, 1), 256, SM1>>>(bias, out);
}

// round 16
// speedup vs baseline: 1.1444x; 1.0081x over previous
#include <cuda_runtime.h>
#include <cuda_fp16.h>
#include <cstdint>

// Problem dims
#define Bq 16
#define Tq 512
#define Eq 256
#define Aq 8

// Scratch (allocation-free rules: __device__ globals)
__device__ float  g_gram[Bq * Tq * Tq];             // masked gram fp32
__device__ __half g_xh [Bq * Tq * Eq];              // X hi (B,T,E)
__device__ __half g_xl [Bq * Tq * Eq];              // X lo (gram 3-pass only)
__device__ __half g_xth[Bq * Eq * Tq];              // X^T hi (B,E,T)
__device__ __half g_attn_h[Bq * Aq * Tq * Tq];      // attn hi fp16 (av A operand)
__device__ __half g_aoh[Bq * Aq * Tq * Eq];         // attn_out hi (B,A,T,E)
__device__ __half g_wh [Eq * Aq * Eq];              // W hi
__device__ float  g_attn_fb[Bq * Aq * Tq * Tq];     // fallback fp32 attn buffer

// GEMM tiling: 128x128 CTA tile, k32 fp-elem stages, 256 threads, 8 warps (4x2)
// smem matrix: 128 rows x 80B (4 x 16B chunks + 16B pad -> ldmatrix conflict-free)
// 1-pass kernels (av/proj): 3-stage cp.async pipeline, 61440 B -> 2 CTAs/SM.
// 3-pass kernel (gram): 3-stage, 122880 B -> 1 CTA/SM.
#define MATB 10240
#define NSTAGE 3

// ---------------------------------------------------------------------------
__device__ __forceinline__ uint32_t smem_u32(const void* p) {
    uint32_t a;
    asm("{ .reg .u64 t; cvta.to.shared.u64 t, %1; cvt.u32.u64 %0, t; }" : "=r"(a) : "l"(p));
    return a;
}
__device__ __forceinline__ void cp16(uint32_t dst, const void* src) {
    asm volatile("cp.async.cg.shared.global [%0], [%1], 16;"
                 :: "r"(dst), "l"(__cvta_generic_to_global(src)));
}
__device__ __forceinline__ void cp_commit() {
    asm volatile("cp.async.commit_group;");
}
template <int N>
__device__ __forceinline__ void cp_wait() {
    asm volatile("cp.async.wait_group %0;" :: "n"(N));
}
__device__ __forceinline__ void ldsm_x4(unsigned& r0, unsigned& r1, unsigned& r2,
                                        unsigned& r3, uint32_t addr) {
    asm volatile("ldmatrix.sync.aligned.m8n8.x4.shared.b16 {%0,%1,%2,%3}, [%4];"
                 : "=r"(r0), "=r"(r1), "=r"(r2), "=r"(r3) : "r"(addr));
}
__device__ __forceinline__ void mma16816(float* c, const unsigned* a, const unsigned* b) {
    asm volatile(
        "mma.sync.aligned.m16n8k16.row.col.f32.f16.f16.f32 "
        "{%0,%1,%2,%3}, {%4,%5,%6,%7}, {%8,%9}, {%0,%1,%2,%3};"
        : "+f"(c[0]), "+f"(c[1]), "+f"(c[2]), "+f"(c[3])
        : "r"(a[0]), "r"(a[1]), "r"(a[2]), "r"(a[3]), "r"(b[0]), "r"(b[1]));
}

// ---------------------------------------------------------------------------
// MMA compute over one k32 stage (warp tile 32x64, 4x2 warp grid).
// NPASS==1: ah*bh only.        A at abase,       B at bbase.
// NPASS==3: + al*bh + ah*bl.   Al at abase+MATB, Bl at bbase+MATB.
// ---------------------------------------------------------------------------
template <int NPASS>
__device__ __forceinline__ void mma_stage(uint32_t abase, uint32_t bbase,
                                          float acc[2][8][4]) {
    const int lane = threadIdx.x & 31, wid = threadIdx.x >> 5;
    const int mw = (wid >> 1) * 32, nw = (wid & 1) * 64;
    const int lr = lane & 7, q = lane >> 3;
    const int a_ro = (q & 1) * 8 + lr, a_co = (q >> 1);
    const int b_ro = (q >> 1) * 8 + lr, b_co = (q & 1);
    #pragma unroll
    for (int ks = 0; ks < 2; ++ks) {
        unsigned ah[2][4], al[2][4];
        #pragma unroll
        for (int mt = 0; mt < 2; ++mt) {
            uint32_t ad = abase + (uint32_t)((mw + mt * 16 + a_ro) * 80 + (2 * ks + a_co) * 16);
            ldsm_x4(ah[mt][0], ah[mt][1], ah[mt][2], ah[mt][3], ad);
            if (NPASS == 3)
                ldsm_x4(al[mt][0], al[mt][1], al[mt][2], al[mt][3], ad + MATB);
        }
        unsigned bh[8][2], bl[8][2];
        #pragma unroll
        for (int np = 0; np < 4; ++np) {
            uint32_t bd = bbase + (uint32_t)((nw + np * 16 + b_ro) * 80 + (2 * ks + b_co) * 16);
            ldsm_x4(bh[2*np][0], bh[2*np][1], bh[2*np+1][0], bh[2*np+1][1], bd);
            if (NPASS == 3)
                ldsm_x4(bl[2*np][0], bl[2*np][1], bl[2*np+1][0], bl[2*np+1][1], bd + MATB);
        }
        #pragma unroll
        for (int nt = 0; nt < 8; ++nt)
            #pragma unroll
            for (int mt = 0; mt < 2; ++mt) {
                mma16816(acc[mt][nt], ah[mt], bh[nt]);
                if (NPASS == 3) {
                    mma16816(acc[mt][nt], al[mt], bh[nt]);
                    mma16816(acc[mt][nt], ah[mt], bl[nt]);
                }
            }
    }
}

// ---------------------------------------------------------------------------
// Mainloop: pre-split fp16 planes in gmem, all via cp.async. 3-stage pipeline.
// NPASS==1: stage = {Ah, Bh};  NPASS==3: stage = {Ah, Al, Bh, Bl}.
// ---------------------------------------------------------------------------
template <int NPASS>
__device__ __forceinline__ void mma_loop(
    const __half* __restrict__ Agh, const __half* __restrict__ Agl, int lda, int m0,
    const __half* __restrict__ Bgh, const __half* __restrict__ Bgl, int ldb, int n0,
    int kIters, char* smb, float acc[2][8][4])
{
    const int BOFF  = (NPASS == 3 ? 2 : 1) * MATB;
    const int STAGE = (NPASS == 3 ? 4 : 2) * MATB;
    const int t = threadIdx.x;
    const int r = t >> 1, cb = (t & 1) * 2;
    const __half* pa_h = Agh + (size_t)(m0 + r) * lda + cb * 8;
    const __half* pa_l = (NPASS == 3) ? Agl + (size_t)(m0 + r) * lda + cb * 8 : pa_h;
    const __half* pb_h = Bgh + (size_t)(n0 + r) * ldb + cb * 8;
    const __half* pb_l = (NPASS == 3) ? Bgl + (size_t)(n0 + r) * ldb + cb * 8 : pb_h;
    const uint32_t sbase = smem_u32(smb);
    const uint32_t rowoff = (uint32_t)r * 80u + (uint32_t)cb * 16u;

    auto issue = [&](int it) {
        uint32_t sb = sbase + (uint32_t)((it % NSTAGE) * STAGE) + rowoff;
        int k0 = it * 32;
        #pragma unroll
        for (int j = 0; j < 2; ++j) {
            cp16(sb + j * 16,        pa_h + k0 + j * 8);
            cp16(sb + BOFF + j * 16, pb_h + k0 + j * 8);
            if (NPASS == 3) {
                cp16(sb + MATB + j * 16,     pa_l + k0 + j * 8);
                cp16(sb + 3 * MATB + j * 16, pb_l + k0 + j * 8);
            }
        }
    };
    issue(0); cp_commit();
    issue(1); cp_commit();

    for (int it = 0; it < kIters; ++it) {
        cp_wait<1>();
        __syncthreads();
        if (it + 2 < kIters) issue(it + 2);
        cp_commit();
        uint32_t sb = sbase + (uint32_t)((it % NSTAGE) * STAGE);
        mma_stage<NPASS>(sb, sb + BOFF, acc);
    }
}

// ---------------------------------------------------------------------------
// Kernel 0a: X -> Xh, Xl (B,T,E) and Xth (B,E,T)
// ---------------------------------------------------------------------------
__global__ void prep_x_kernel(const float* __restrict__ X) {
    __shared__ float tile[32][33];
    int b = blockIdx.z;
    int e0 = blockIdx.x * 32, t0 = blockIdx.y * 32;
    const float* Xb = X + (size_t)b * Tq * Eq;
    int tx = threadIdx.x, ty = threadIdx.y;  // 32x8
    #pragma unroll
    for (int i = 0; i < 32; i += 8) {
        float v = Xb[(size_t)(t0 + ty + i) * Eq + e0 + tx];
        tile[ty + i][tx] = v;
        __half h = __float2half_rn(v);
        __half l = __float2half_rn(v - __half2float(h));
        size_t idx = ((size_t)b * Tq + t0 + ty + i) * Eq + e0 + tx;
        g_xh[idx] = h;
        g_xl[idx] = l;
    }
    __syncthreads();
    #pragma unroll
    for (int i = 0; i < 32; i += 8) {
        float v = tile[tx][ty + i];
        g_xth[((size_t)b * Eq + e0 + ty + i) * Tq + t0 + tx] = __float2half_rn(v);
    }
}

// Kernel 0b: W -> Wh
__global__ void prep_w_kernel(const float* __restrict__ W) {
    int idx = blockIdx.x * 256 + threadIdx.x;
    g_wh[idx] = __float2half_rn(W[idx]);
}

// ---------------------------------------------------------------------------
// Kernel 1: G_b = mask-outer ? (X_b X_b^T)/sqrt(E) : 0   (3-pass fp16, K=256)
// ---------------------------------------------------------------------------
__global__ __launch_bounds__(256, 1)
void gram_kernel(const int* __restrict__ mask) {
    extern __shared__ char smb[];
    int b = blockIdx.z;
    int m0 = blockIdx.y * 128, n0 = blockIdx.x * 128;
    const __half* Xh = g_xh + (size_t)b * Tq * Eq;
    const __half* Xl = g_xl + (size_t)b * Tq * Eq;
    float acc[2][8][4] = {};
    mma_loop<3>(Xh, Xl, Eq, m0, Xh, Xl, Eq, n0, Eq / 32, smb, acc);

    const int lane = threadIdx.x & 31, wid = threadIdx.x >> 5;
    const int gid = lane >> 2, tig = lane & 3;
    const int mw = (wid >> 1) * 32, nw = (wid & 1) * 64;
    const int* mb = mask + b * Tq;
    float* G = g_gram + (size_t)b * Tq * Tq;
    #pragma unroll
    for (int mt = 0; mt < 2; ++mt) {
        int mr0 = m0 + mw + mt * 16 + gid;
        int mr1 = mr0 + 8;
        float s0 = (mb[mr0] != 0) ? 0.0625f : 0.0f;   // 1/sqrt(256), fold row mask
        float s1 = (mb[mr1] != 0) ? 0.0625f : 0.0f;
        #pragma unroll
        for (int nt = 0; nt < 8; ++nt) {
            int col = n0 + nw + nt * 8 + 2 * tig;
            float c0 = (mb[col] != 0) ? 1.0f : 0.0f;
            float c1 = (mb[col + 1] != 0) ? 1.0f : 0.0f;
            *(float2*)&G[(size_t)mr0 * Tq + col] =
                make_float2(acc[mt][nt][0] * s0 * c0, acc[mt][nt][1] * s0 * c1);
            *(float2*)&G[(size_t)mr1 * Tq + col] =
                make_float2(acc[mt][nt][2] * s1 * c0, acc[mt][nt][3] * s1 * c1);
        }
    }
}

// ---------------------------------------------------------------------------
// Kernel 2: softmax, warp-per-attribute; zero barriers; writes fp32 + fp16 hi
// ---------------------------------------------------------------------------
__global__ __launch_bounds__(256, 8)
void softmax_kernel(const float* __restrict__ atr, float* __restrict__ attn) {
    int t = blockIdx.x, b = blockIdx.y;
    int wid = threadIdx.x >> 5, lane = threadIdx.x & 31;
    const float4* g4 = (const float4*)(g_gram + ((size_t)b * Tq + t) * Tq);
    float4 v[4];
    #pragma unroll
    for (int j = 0; j < 4; ++j) v[j] = g4[lane + 32 * j];

    float m = v[0].x;
    #pragma unroll
    for (int j = 0; j < 4; ++j) {
        m = fmaxf(m, fmaxf(fmaxf(v[j].x, v[j].y), fmaxf(v[j].z, v[j].w)));
    }
    #pragma unroll
    for (int off = 16; off; off >>= 1) m = fmaxf(m, __shfl_xor_sync(0xffffffffu, m, off));

    float s = atr[b * Aq + wid];
    float s2 = s * s;
    float4 e[4];
    float sum = 0.0f;
    #pragma unroll
    for (int j = 0; j < 4; ++j) {
        e[j].x = __expf(s2 * (v[j].x - m));
        e[j].y = __expf(s2 * (v[j].y - m));
        e[j].z = __expf(s2 * (v[j].z - m));
        e[j].w = __expf(s2 * (v[j].w - m));
        sum += e[j].x + e[j].y + e[j].z + e[j].w;
    }
    #pragma unroll
    for (int off = 16; off; off >>= 1) sum += __shfl_xor_sync(0xffffffffu, sum, off);
    float inv = 1.0f / sum;

    size_t rowbase = (((size_t)(b * Aq + wid) * Tq) + t) * Tq;
    float4* o4 = (float4*)(attn + rowbase);
    uint2*  h2 = (uint2*)(g_attn_h + rowbase);
    #pragma unroll
    for (int j = 0; j < 4; ++j) {
        float4 o = make_float4(e[j].x * inv, e[j].y * inv, e[j].z * inv, e[j].w * inv);
        o4[lane + 32 * j] = o;
        __half2 ha = __float22half2_rn(make_float2(o.x, o.y));
        __half2 hb = __float22half2_rn(make_float2(o.z, o.w));
        h2[lane + 32 * j] = make_uint2(*(unsigned*)&ha, *(unsigned*)&hb);
    }
}

// ---------------------------------------------------------------------------
// Kernel 3: attn_out[ba] = s_ba * (attn_ba @ X_b); 128x128, 1-pass, 3-stage
// ---------------------------------------------------------------------------
__global__ __launch_bounds__(256, 2)
void av_kernel(const float* __restrict__ atr) {
    extern __shared__ char smb[];
    int ba = blockIdx.z, b = ba >> 3;
    int m0 = blockIdx.y * 128, n0 = blockIdx.x * 128;
    const __half* Ah = g_attn_h + (size_t)ba * Tq * Tq;
    const __half* Bh = g_xth + (size_t)b * Eq * Tq;
    float acc[2][8][4] = {};
    mma_loop<1>(Ah, nullptr, Tq, m0, Bh, nullptr, Tq, n0, Tq / 32, smb, acc);

    const int lane = threadIdx.x & 31, wid = threadIdx.x >> 5;
    const int gid = lane >> 2, tig = lane & 3;
    const int mw = (wid >> 1) * 32, nw = (wid & 1) * 64;
    float sc = atr[ba];
    #pragma unroll
    for (int mt = 0; mt < 2; ++mt) {
        int mr0 = m0 + mw + mt * 16 + gid;
        int mr1 = mr0 + 8;
        #pragma unroll
        for (int nt = 0; nt < 8; ++nt) {
            int col = n0 + nw + nt * 8 + 2 * tig;
            size_t i0 = ((size_t)ba * Tq + mr0) * Eq + col;
            size_t i1 = ((size_t)ba * Tq + mr1) * Eq + col;
            *(__half2*)&g_aoh[i0] = __float22half2_rn(
                make_float2(sc * acc[mt][nt][0], sc * acc[mt][nt][1]));
            *(__half2*)&g_aoh[i1] = __float22half2_rn(
                make_float2(sc * acc[mt][nt][2], sc * acc[mt][nt][3]));
        }
    }
}

// ---------------------------------------------------------------------------
// Kernel 4a: out = bias (init for split-K accumulation)
// ---------------------------------------------------------------------------
__global__ void bias_init_kernel(const float* __restrict__ bias, float* __restrict__ out) {
    int idx = blockIdx.x * 256 + threadIdx.x;              // over B*T*E/4
    float4 bv = *(const float4*)&bias[(idx & 63) * 4];     // Eq/4=64 float4 per row
    ((float4*)out)[idx] = bv;
}

// ---------------------------------------------------------------------------
// Kernel 4b: out += aoh(8192x2048) @ Wh^T(2048x256), split-K=2, 1-pass
// 256 CTAs -> ~2 CTAs/SM instead of the 128-CTA single-wave starvation.
// ---------------------------------------------------------------------------
__global__ __launch_bounds__(256, 2)
void proj_kernel(float* __restrict__ out) {
    extern __shared__ char smb[];
    const int Kd = Aq * Eq;   // 2048
    const int KS = Kd / 2;    // 1024 per split
    int m0 = blockIdx.y * 128, n0 = blockIdx.x * 128;
    int kBase = blockIdx.z * KS;
    float acc[2][8][4] = {};
    mma_loop<1>(g_aoh + kBase, nullptr, Kd, m0,
                g_wh + kBase, nullptr, Kd, n0, KS / 32, smb, acc);

    const int lane = threadIdx.x & 31, wid = threadIdx.x >> 5;
    const int gid = lane >> 2, tig = lane & 3;
    const int mw = (wid >> 1) * 32, nw = (wid & 1) * 64;
    #pragma unroll
    for (int mt = 0; mt < 2; ++mt) {
        int mr0 = m0 + mw + mt * 16 + gid;
        int mr1 = mr0 + 8;
        #pragma unroll
        for (int nt = 0; nt < 8; ++nt) {
            int col = n0 + nw + nt * 8 + 2 * tig;
            atomicAdd(&out[(size_t)mr0 * Eq + col],     acc[mt][nt][0]);
            atomicAdd(&out[(size_t)mr0 * Eq + col + 1], acc[mt][nt][1]);
            atomicAdd(&out[(size_t)mr1 * Eq + col],     acc[mt][nt][2]);
            atomicAdd(&out[(size_t)mr1 * Eq + col + 1], acc[mt][nt][3]);
        }
    }
}

// ---------------------------------------------------------------------------
extern "C" void kernel_launch(void* const* d_in, const int* in_sizes, int n_in,
                              void* d_out, int out_size) {
    const float* sent = (const float*)d_in[0];
    const int*   mask = (const int*)d_in[1];
    const float* atr  = (const float*)d_in[2];
    const float* W    = (const float*)d_in[3];
    const float* bias = (const float*)d_in[4];
    float* out = (float*)d_out;

    const long long OUT_E  = (long long)Bq * Tq * Eq;        // 2,097,152
    const long long ATTN_E = (long long)Bq * Aq * Tq * Tq;   // 33,554,432

    float* attn_ptr;
    if ((long long)out_size >= OUT_E + ATTN_E) {
        attn_ptr = out + OUT_E;                  // tuple (output, attn) flattened
    } else {
        void* p = nullptr;
        cudaGetSymbolAddress(&p, g_attn_fb);     // query only, capture-safe
        attn_ptr = (float*)p;
    }

    const int SM3 = 3 * 4 * MATB;   // 122880 (gram 3-pass: 3 stages x 4 mats)
    const int SM1 = 3 * 2 * MATB;   // 61440  (1-pass: 3 stages x 2 mats, 2 CTAs/SM)
    cudaFuncSetAttribute(gram_kernel, cudaFuncAttributeMaxDynamicSharedMemorySize, SM3);
    cudaFuncSetAttribute(av_kernel,   cudaFuncAttributeMaxDynamicSharedMemorySize, SM1);
    cudaFuncSetAttribute(proj_kernel, cudaFuncAttributeMaxDynamicSharedMemorySize, SM1);

    prep_x_kernel<<<dim3(Eq / 32, Tq / 32, Bq), dim3(32, 8)>>>(sent);
    prep_w_kernel<<<(Eq * Aq * Eq) / 256, 256>>>(W);
    gram_kernel<<<dim3(Tq / 128, Tq / 128, Bq), 256, SM3>>>(mask);
    softmax_kernel<<<dim3(Tq, Bq), 256>>>(atr, attn_ptr);
    av_kernel<<<dim3(Eq / 128, Tq / 128, Bq * Aq), 256, SM1>>>(atr);
    bias_init_kernel<<<(Bq * Tq * Eq / 4) / 256, 256>>>(bias, out);
    proj_kernel<<<dim3(Eq / 128, (Bq * Tq) / 128, 2), 256, SM1>>>(out);
}